// round 9
// baseline (speedup 1.0000x reference)
#include <cuda_runtime.h>

// VideoEmbedding: out[n,d] = sum_k basis(t_n)[k] * W[vid_n, d, k]
// N=400000, D=64, K=13, V=128.
//
// SINGLE persistent kernel (grid = max co-resident blocks, runtime-derived):
//  Phase A: weight transpose [v][d][k]->[v][k][d] + per-block smem-rank
//           histogram (ranks in registers) -> count matrix [v][b]
//  Grid barrier 1 (ticket)
//           per-block scatter bases from unrolled int4 row sums +
//           32-padded segment scan (each block computes full table in smem)
//           -> scatter n-indices to g_sorted
//  Grid barrier 2
//  Phase B: warps own consecutive 32-chunk ranges; chunk->video via smem
//           binary search + walk; W[v] register-resident (13 f32x2/lane,
//           lane owns d=2*lane..+1), reloaded only on video change; basis
//           via one __sincosf + double-angle recurrence splatted to smem;
//           inner: 6 broadcast LDS.128 + 14 packed f32x2 FMA + STG.64.

static constexpr int D  = 64;
static constexpr int K  = 13;
static constexpr int MAXV = 256;
static constexpr int SORT_CAP = 1 << 20;
static constexpr int GMAX = 1024;
static constexpr int TPB  = 256;
static constexpr int NU   = 4;     // int4 slots per thread in phase A

__device__ float g_wt[MAXV * K * D];
__device__ int   g_cnt[MAXV * GMAX];   // [v][b]
__device__ int   g_sorted[SORT_CAP];   // never-written pad slots stay 0
__device__ int   g_bar, g_fin;

typedef unsigned long long ull;

__device__ __forceinline__ ull ffma2u(ull a, ull b, ull c) {
    ull d;
    asm("fma.rn.f32x2 %0, %1, %2, %3;" : "=l"(d) : "l"(a), "l"(b), "l"(c));
    return d;
}
__device__ __forceinline__ ull fmul2u(ull a, ull b) {
    ull d;
    asm("mul.rn.f32x2 %0, %1, %2;" : "=l"(d) : "l"(a), "l"(b));
    return d;
}
__device__ __forceinline__ ull fadd2u(ull a, ull b) {
    ull d;
    asm("add.rn.f32x2 %0, %1, %2;" : "=l"(d) : "l"(a), "l"(b));
    return d;
}
__device__ __forceinline__ ull splat2(float x) {
    ull r;
    asm("mov.b64 %0, {%1, %1};" : "=l"(r) : "f"(x));
    return r;
}

__global__ void __launch_bounds__(TPB, 4)
k_all(const float* __restrict__ w, const int* __restrict__ vids,
      const float* __restrict__ times, float* __restrict__ out,
      int N, int V, int tile, int G) {
    __shared__ int s_rk[MAXV];        // rank counters -> scan scratch
    __shared__ int s_base[MAXV];      // this block's scatter bases
    __shared__ int s_start[MAXV + 1]; // padded segment starts (+ total)
    __shared__ int s_end[MAXV];       // real segment ends
    __shared__ __align__(16) ull smb[8][32 * 12];  // per-warp basis staging
    __shared__ int sidx[8][32];

    const int tid = threadIdx.x, b = blockIdx.x;
    for (int i = tid; i < MAXV; i += TPB) s_rk[i] = 0;
    __syncthreads();

    // ---- Phase A: transpose ----
    const int total = V * D * K;
    for (int i = b * TPB + tid; i < total; i += G * TPB) {
        int k = i % K;
        int d = (i / K) % D;
        int v = i / (K * D);
        g_wt[(v * K + k) * D + d] = w[i];
    }

    // ---- Phase A: histogram, ranks held in registers ----
    const int start = b * tile;               // tile is 4-aligned
    const int end   = min(start + tile, N);
    const int s4 = start >> 2, e4 = end >> 2;
    int4 q[NU]; int rk[NU][4]; bool hv[NU];
#pragma unroll
    for (int u = 0; u < NU; u++) {
        const int i4 = s4 + u * TPB + tid;
        hv[u] = (i4 < e4);
        if (hv[u]) {
            q[u] = reinterpret_cast<const int4*>(vids)[i4];
            rk[u][0] = atomicAdd(&s_rk[q[u].x], 1);
            rk[u][1] = atomicAdd(&s_rk[q[u].y], 1);
            rk[u][2] = atomicAdd(&s_rk[q[u].z], 1);
            rk[u][3] = atomicAdd(&s_rk[q[u].w], 1);
        }
    }
    int tval = -1, trk = 0;
    const int ti = (e4 << 2) + tid;
    if (ti < end) { tval = vids[ti]; trk = atomicAdd(&s_rk[tval], 1); }
    __syncthreads();

    for (int i = tid; i < MAXV; i += TPB)
        g_cnt[i * GMAX + b] = s_rk[i];
    __threadfence();

    // ---- grid barrier 1 ----
    if (tid == 0) {
        atomicAdd(&g_bar, 1);
        volatile int* vb = &g_bar;
        while (*vb < G) { }
    }
    __syncthreads();

    // ---- bases + padded scan (every block computes full table) ----
    int prior = 0, totv = 0;
    if (tid < MAXV) {
        const int4* row = reinterpret_cast<const int4*>(g_cnt + tid * GMAX);
        const int nq = G >> 2;                 // G is a multiple of 4
#pragma unroll 8
        for (int qi = 0; qi < nq; qi++) {
            const int4 c = row[qi];
            const int bb = qi * 4;
            totv  += c.x + c.y + c.z + c.w;
            prior += (bb     < b ? c.x : 0) + (bb + 1 < b ? c.y : 0)
                   + (bb + 2 < b ? c.z : 0) + (bb + 3 < b ? c.w : 0);
        }
        s_rk[tid] = (totv + 31) & ~31;
    }
    __syncthreads();
    for (int s = 1; s < MAXV; s <<= 1) {       // inclusive scan
        int a = (tid < MAXV && tid >= s) ? s_rk[tid - s] : 0;
        __syncthreads();
        if (tid < MAXV) s_rk[tid] += a;
        __syncthreads();
    }
    if (tid < MAXV) {
        const int pad = (totv + 31) & ~31;
        const int segoff = s_rk[tid] - pad;    // exclusive padded offset
        s_base[tid]  = segoff + prior;
        s_start[tid] = segoff;
        s_end[tid]   = segoff + totv;
        if (tid == MAXV - 1) s_start[MAXV] = s_rk[tid];
    }
    __syncthreads();
    const int NC = s_start[MAXV] >> 5;

    // ---- scatter ----
#pragma unroll
    for (int u = 0; u < NU; u++) {
        if (hv[u]) {
            const int base = (s4 + u * TPB + tid) << 2;
            g_sorted[s_base[q[u].x] + rk[u][0]] = base;
            g_sorted[s_base[q[u].y] + rk[u][1]] = base + 1;
            g_sorted[s_base[q[u].z] + rk[u][2]] = base + 2;
            g_sorted[s_base[q[u].w] + rk[u][3]] = base + 3;
        }
    }
    if (tval >= 0) g_sorted[s_base[tval] + trk] = ti;
    __threadfence();

    // ---- grid barrier 2 ----
    if (tid == 0) {
        atomicAdd(&g_bar, 1);
        volatile int* vb = &g_bar;
        while (*vb < 2 * G) { }
    }
    __syncthreads();

    // ---- Phase B: main compute ----
    const int lane = tid & 31;
    const int wib  = tid >> 5;
    const int gwarp = b * 8 + wib;
    const int TW = G * 8;
    const int L = (NC + TW - 1) / TW;
    const int cbeg = gwarp * L;
    const int cend = min(cbeg + L, NC);

    if (cbeg < cend) {
        // binary search: largest v with s_start[v] <= cbeg*32
        int v = 0;
        {
            const int pos = cbeg * 32;
#pragma unroll
            for (int step = 128; step; step >>= 1) {
                const int nv = v + step;
                if (nv <= MAXV - 1 && s_start[nv] <= pos) v = nv;
            }
        }
        int vprev = -1;
        ull wreg[K];

        for (int c = cbeg; c < cend; c++) {
            const int pos = c * 32;
            while (pos >= s_start[v + 1]) v++;     // warp-uniform walk

            const int idx = g_sorted[pos + lane];  // pad slots are 0 (valid)
            if (v != vprev) {
                const float* wp = g_wt + v * (K * D) + 2 * lane;
#pragma unroll
                for (int k = 0; k < K; k++)
                    wreg[k] = *reinterpret_cast<const ull*>(wp + k * D);
                vprev = v;
            }

            const float t = times[idx];
            const float a = t * 3.14159265358979323846f;
            float s1, q1; __sincosf(a, &s1, &q1);
            const float s2 = 2.f * s1 * q1, q2 = fmaf(q1, q1, -s1 * s1);
            const float s3 = 2.f * s2 * q2, q3 = fmaf(q2, q2, -s2 * s2);
            const float s4b = 2.f * s3 * q3, q4 = fmaf(q3, q3, -s3 * s3);
            const float s5 = 2.f * s4b * q4, q5 = fmaf(q4, q4, -s4b * s4b);
            const float s6 = 2.f * s5 * q5, q6 = fmaf(q5, q5, -s5 * s5);

            ulonglong2* bl =
                reinterpret_cast<ulonglong2*>(&smb[wib][lane * 12]);
            bl[0] = make_ulonglong2(splat2(s1), splat2(s2));
            bl[1] = make_ulonglong2(splat2(s3), splat2(s4b));
            bl[2] = make_ulonglong2(splat2(s5), splat2(s6));
            bl[3] = make_ulonglong2(splat2(q1), splat2(q2));
            bl[4] = make_ulonglong2(splat2(q3), splat2(q4));
            bl[5] = make_ulonglong2(splat2(q5), splat2(q6));
            sidx[wib][lane] = idx;
            __syncwarp();

            const int jmax = min(32, s_end[v] - pos);   // >= 1, warp-uniform
            for (int j = 0; j < jmax; j++) {
                const int nn = sidx[wib][j];
                const ulonglong2* bj =
                    reinterpret_cast<const ulonglong2*>(&smb[wib][j * 12]);
                const ulonglong2 P0 = bj[0], P1 = bj[1], P2 = bj[2];
                const ulonglong2 P3 = bj[3], P4 = bj[4], P5 = bj[5];
                ull a0 = ffma2u(P0.x, wreg[1], wreg[0]);  // basis[0]==1
                ull a1 = fmul2u(P0.y, wreg[2]);
                a0 = ffma2u(P1.x, wreg[3],  a0);
                a1 = ffma2u(P1.y, wreg[4],  a1);
                a0 = ffma2u(P2.x, wreg[5],  a0);
                a1 = ffma2u(P2.y, wreg[6],  a1);
                a0 = ffma2u(P3.x, wreg[7],  a0);
                a1 = ffma2u(P3.y, wreg[8],  a1);
                a0 = ffma2u(P4.x, wreg[9],  a0);
                a1 = ffma2u(P4.y, wreg[10], a1);
                a0 = ffma2u(P5.x, wreg[11], a0);
                a1 = ffma2u(P5.y, wreg[12], a1);
                *reinterpret_cast<ull*>(out + (long)nn * D + 2 * lane) =
                    fadd2u(a0, a1);
            }
            __syncwarp();
        }
    }

    // ---- exit ticket: reset barrier counters for next graph replay ----
    __threadfence();
    if (tid == 0) {
        if (atomicAdd(&g_fin, 1) == G - 1) { g_bar = 0; g_fin = 0; }
    }
}

extern "C" void kernel_launch(void* const* d_in, const int* in_sizes, int n_in,
                              void* d_out, int out_size) {
    const float* times   = (const float*)d_in[0];
    const int*   vids    = (const int*)d_in[1];
    const float* weights = (const float*)d_in[2];
    float*       out     = (float*)d_out;

    const int N = in_sizes[0];
    int V = in_sizes[2] / (D * K);
    if (V > MAXV) V = MAXV;

    int dev = 0;
    cudaGetDevice(&dev);
    int sms = 148;
    cudaDeviceGetAttribute(&sms, cudaDevAttrMultiProcessorCount, dev);
    int nb = 0;
    cudaOccupancyMaxActiveBlocksPerMultiprocessor(&nb, k_all, TPB, 0);
    if (nb < 1) nb = 1;
    int G = nb * sms;
    if (G > GMAX) G = GMAX;

    const int tile = (((N + G - 1) / G) + 3) & ~3;   // 4-aligned
    k_all<<<G, TPB>>>(weights, vids, times, out, N, V, tile, G);
}

// round 10
// speedup vs baseline: 2.5064x; 2.5064x over previous
#include <cuda_runtime.h>

// VideoEmbedding: out[n,d] = sum_k basis(t_n)[k] * W[vid_n, d, k]
// N=400000, D=64, K=13, V=128.
//
// SINGLE persistent kernel, single co-resident wave (G = occupancy-derived):
//  Phase A: weight transpose + per-block smem-rank histogram (ranks in regs)
//           -> count row g_cnt[v][b]
//  barrier1
//  Phase S: block v (v<V) block-scans video v's count row (G entries) ->
//           per-block bases g_base[b][v] + total g_segtot[v]   (O(G*V) total)
//  barrier2
//  Phase C: each block loads its OWN bases + totals, 32-padded segment scan
//           in smem, scatters n-indices to g_sorted
//  barrier3
//  Phase B: warps own consecutive 32-chunk ranges; chunk->video via smem
//           binary search + walk; W[v] register-resident (13 f32x2/lane),
//           basis via __sincosf + double-angle recurrence splatted to smem;
//           inner: 6 broadcast LDS.128 + 13 packed f32x2 FMA + STG.64.
//  All barrier spins use __nanosleep backoff (R9's hot volatile spin was
//  hammering one L2 line from every block: L1=84%, issue=18.6%).

static constexpr int D  = 64;
static constexpr int K  = 13;
static constexpr int MAXV = 256;
static constexpr int SORT_CAP = 1 << 20;
static constexpr int GMAX = 1024;
static constexpr int TPB  = 256;
static constexpr int NU   = 4;     // int4 slots per thread in phase A

__device__ float g_wt[MAXV * K * D];
__device__ int   g_cnt[MAXV * GMAX];    // [v][b]
__device__ int   g_base[GMAX * MAXV];   // [b][v] scatter bases (pre-segoff)
__device__ int   g_segtot[MAXV];
__device__ int   g_sorted[SORT_CAP];    // never-written pad slots stay 0
__device__ int   g_bar, g_fin;

typedef unsigned long long ull;

__device__ __forceinline__ ull ffma2u(ull a, ull b, ull c) {
    ull d;
    asm("fma.rn.f32x2 %0, %1, %2, %3;" : "=l"(d) : "l"(a), "l"(b), "l"(c));
    return d;
}
__device__ __forceinline__ ull fmul2u(ull a, ull b) {
    ull d;
    asm("mul.rn.f32x2 %0, %1, %2;" : "=l"(d) : "l"(a), "l"(b));
    return d;
}
__device__ __forceinline__ ull fadd2u(ull a, ull b) {
    ull d;
    asm("add.rn.f32x2 %0, %1, %2;" : "=l"(d) : "l"(a), "l"(b));
    return d;
}
__device__ __forceinline__ ull splat2(float x) {
    ull r;
    asm("mov.b64 %0, {%1, %1};" : "=l"(r) : "f"(x));
    return r;
}

__device__ __forceinline__ void grid_barrier(int tid, int target) {
    __threadfence();
    __syncthreads();
    if (tid == 0) {
        atomicAdd(&g_bar, 1);
        volatile int* vb = &g_bar;
        while (*vb < target) __nanosleep(32);
    }
    __syncthreads();
}

__global__ void __launch_bounds__(TPB, 4)
k_all(const float* __restrict__ w, const int* __restrict__ vids,
      const float* __restrict__ times, float* __restrict__ out,
      int N, int V, int tile, int G) {
    __shared__ int s_rk[MAXV];        // rank counters -> scan scratch
    __shared__ int s_base[MAXV];      // this block's scatter bases
    __shared__ int s_start[MAXV + 1]; // padded segment starts (+ total)
    __shared__ int s_end[MAXV];       // real segment ends
    __shared__ __align__(16) ull smb[8][32 * 12];  // basis staging / scratch
    __shared__ int sidx[8][32];

    const int tid = threadIdx.x, b = blockIdx.x;
    for (int i = tid; i < MAXV; i += TPB) s_rk[i] = 0;
    __syncthreads();

    // ---- Phase A: transpose [v][d][k] -> [v][k][d] ----
    const int total = V * D * K;
    for (int i = b * TPB + tid; i < total; i += G * TPB) {
        int k = i % K;
        int d = (i / K) % D;
        int v = i / (K * D);
        g_wt[(v * K + k) * D + d] = w[i];
    }

    // ---- Phase A: histogram, ranks held in registers ----
    const int start = b * tile;               // tile is 4-aligned
    const int end   = min(start + tile, N);
    const int s4 = start >> 2, e4 = end >> 2;
    int4 q[NU]; int rk[NU][4]; bool hv[NU];
#pragma unroll
    for (int u = 0; u < NU; u++) {
        const int i4 = s4 + u * TPB + tid;
        hv[u] = (i4 < e4);
        if (hv[u]) {
            q[u] = reinterpret_cast<const int4*>(vids)[i4];
            rk[u][0] = atomicAdd(&s_rk[q[u].x], 1);
            rk[u][1] = atomicAdd(&s_rk[q[u].y], 1);
            rk[u][2] = atomicAdd(&s_rk[q[u].z], 1);
            rk[u][3] = atomicAdd(&s_rk[q[u].w], 1);
        }
    }
    int tval = -1, trk = 0;
    const int ti = (e4 << 2) + tid;
    if (ti < end) { tval = vids[ti]; trk = atomicAdd(&s_rk[tval], 1); }
    __syncthreads();

    for (int i = tid; i < V; i += TPB)
        g_cnt[i * GMAX + b] = s_rk[i];

    grid_barrier(tid, G);

    // ---- Phase S: block v scans video v's count row (cooperative) ----
    int* s_scan = reinterpret_cast<int*>(smb);   // 256 ints of scratch
    for (int v = b; v < V; v += G) {
        int4 c = make_int4(0, 0, 0, 0);
        const int bb = tid * 4;
        if (bb < G)
            c = *reinterpret_cast<const int4*>(g_cnt + v * GMAX + bb);
        const int lsum = c.x + c.y + c.z + c.w;
        s_scan[tid] = lsum;
        __syncthreads();
        for (int s = 1; s < TPB; s <<= 1) {       // inclusive block scan
            int a = (tid >= s) ? s_scan[tid - s] : 0;
            __syncthreads();
            s_scan[tid] += a;
            __syncthreads();
        }
        int excl = s_scan[tid] - lsum;
        if (bb < G) {
            g_base[(bb    ) * MAXV + v] = excl;
            g_base[(bb + 1) * MAXV + v] = excl + c.x;
            g_base[(bb + 2) * MAXV + v] = excl + c.x + c.y;
            g_base[(bb + 3) * MAXV + v] = excl + c.x + c.y + c.z;
        }
        if (tid == TPB - 1) g_segtot[v] = s_scan[tid];
        __syncthreads();
    }

    grid_barrier(tid, 2 * G);

    // ---- Phase C: own bases + padded segment scan + scatter ----
    int totv = 0;
    if (tid < MAXV) {
        totv = (tid < V) ? g_segtot[tid] : 0;
        s_rk[tid] = (totv + 31) & ~31;
    }
    __syncthreads();
    for (int s = 1; s < MAXV; s <<= 1) {          // inclusive scan over videos
        int a = (tid < MAXV && tid >= s) ? s_rk[tid - s] : 0;
        __syncthreads();
        if (tid < MAXV) s_rk[tid] += a;
        __syncthreads();
    }
    if (tid < MAXV) {
        const int pad = (totv + 31) & ~31;
        const int segoff = s_rk[tid] - pad;       // exclusive padded offset
        s_start[tid] = segoff;
        s_end[tid]   = segoff + totv;
        if (tid < V) s_base[tid] = segoff + g_base[b * MAXV + tid];
        if (tid == MAXV - 1) s_start[MAXV] = s_rk[tid];
    }
    __syncthreads();
    const int NC = s_start[MAXV] >> 5;

#pragma unroll
    for (int u = 0; u < NU; u++) {
        if (hv[u]) {
            const int base = (s4 + u * TPB + tid) << 2;
            g_sorted[s_base[q[u].x] + rk[u][0]] = base;
            g_sorted[s_base[q[u].y] + rk[u][1]] = base + 1;
            g_sorted[s_base[q[u].z] + rk[u][2]] = base + 2;
            g_sorted[s_base[q[u].w] + rk[u][3]] = base + 3;
        }
    }
    if (tval >= 0) g_sorted[s_base[tval] + trk] = ti;

    grid_barrier(tid, 3 * G);

    // ---- Phase B: main compute ----
    const int lane = tid & 31;
    const int wib  = tid >> 5;
    const int gwarp = b * 8 + wib;
    const int TW = G * 8;
    const int L = (NC + TW - 1) / TW;
    const int cbeg = gwarp * L;
    const int cend = min(cbeg + L, NC);

    if (cbeg < cend) {
        int v = 0;
        {
            const int pos = cbeg * 32;
#pragma unroll
            for (int step = 128; step; step >>= 1) {
                const int nv = v + step;
                if (nv <= MAXV - 1 && s_start[nv] <= pos) v = nv;
            }
        }
        int vprev = -1;
        ull wreg[K];

        for (int c = cbeg; c < cend; c++) {
            const int pos = c * 32;
            while (pos >= s_start[v + 1]) v++;     // warp-uniform walk

            const int idx = g_sorted[pos + lane];  // pad slots are 0 (valid)
            if (v != vprev) {
                const float* wp = g_wt + v * (K * D) + 2 * lane;
#pragma unroll
                for (int k = 0; k < K; k++)
                    wreg[k] = *reinterpret_cast<const ull*>(wp + k * D);
                vprev = v;
            }

            const float t = times[idx];
            const float a = t * 3.14159265358979323846f;
            float s1, q1; __sincosf(a, &s1, &q1);
            const float s2 = 2.f * s1 * q1, q2 = fmaf(q1, q1, -s1 * s1);
            const float s3 = 2.f * s2 * q2, q3 = fmaf(q2, q2, -s2 * s2);
            const float s4b = 2.f * s3 * q3, q4 = fmaf(q3, q3, -s3 * s3);
            const float s5 = 2.f * s4b * q4, q5 = fmaf(q4, q4, -s4b * s4b);
            const float s6 = 2.f * s5 * q5, q6 = fmaf(q5, q5, -s5 * s5);

            ulonglong2* bl =
                reinterpret_cast<ulonglong2*>(&smb[wib][lane * 12]);
            bl[0] = make_ulonglong2(splat2(s1), splat2(s2));
            bl[1] = make_ulonglong2(splat2(s3), splat2(s4b));
            bl[2] = make_ulonglong2(splat2(s5), splat2(s6));
            bl[3] = make_ulonglong2(splat2(q1), splat2(q2));
            bl[4] = make_ulonglong2(splat2(q3), splat2(q4));
            bl[5] = make_ulonglong2(splat2(q5), splat2(q6));
            sidx[wib][lane] = idx;
            __syncwarp();

            const int jmax = min(32, s_end[v] - pos);   // >= 1, warp-uniform
            for (int j = 0; j < jmax; j++) {
                const int nn = sidx[wib][j];
                const ulonglong2* bj =
                    reinterpret_cast<const ulonglong2*>(&smb[wib][j * 12]);
                const ulonglong2 P0 = bj[0], P1 = bj[1], P2 = bj[2];
                const ulonglong2 P3 = bj[3], P4 = bj[4], P5 = bj[5];
                ull a0 = ffma2u(P0.x, wreg[1], wreg[0]);  // basis[0]==1
                ull a1 = fmul2u(P0.y, wreg[2]);
                a0 = ffma2u(P1.x, wreg[3],  a0);
                a1 = ffma2u(P1.y, wreg[4],  a1);
                a0 = ffma2u(P2.x, wreg[5],  a0);
                a1 = ffma2u(P2.y, wreg[6],  a1);
                a0 = ffma2u(P3.x, wreg[7],  a0);
                a1 = ffma2u(P3.y, wreg[8],  a1);
                a0 = ffma2u(P4.x, wreg[9],  a0);
                a1 = ffma2u(P4.y, wreg[10], a1);
                a0 = ffma2u(P5.x, wreg[11], a0);
                a1 = ffma2u(P5.y, wreg[12], a1);
                *reinterpret_cast<ull*>(out + (long)nn * D + 2 * lane) =
                    fadd2u(a0, a1);
            }
            __syncwarp();
        }
    }

    // ---- exit ticket: reset barrier counters for next graph replay ----
    __threadfence();
    if (tid == 0) {
        if (atomicAdd(&g_fin, 1) == G - 1) { g_bar = 0; g_fin = 0; }
    }
}

extern "C" void kernel_launch(void* const* d_in, const int* in_sizes, int n_in,
                              void* d_out, int out_size) {
    const float* times   = (const float*)d_in[0];
    const int*   vids    = (const int*)d_in[1];
    const float* weights = (const float*)d_in[2];
    float*       out     = (float*)d_out;

    const int N = in_sizes[0];
    int V = in_sizes[2] / (D * K);
    if (V > MAXV) V = MAXV;

    int dev = 0;
    cudaGetDevice(&dev);
    int sms = 148;
    cudaDeviceGetAttribute(&sms, cudaDevAttrMultiProcessorCount, dev);
    int nb = 0;
    cudaOccupancyMaxActiveBlocksPerMultiprocessor(&nb, k_all, TPB, 0);
    if (nb < 1) nb = 1;
    int G = nb * sms;
    if (G > GMAX) G = GMAX;
    G &= ~3;                                  // multiple of 4 (int4 row reads)

    const int tile = (((N + G - 1) / G) + 3) & ~3;   // 4-aligned
    k_all<<<G, TPB>>>(weights, vids, times, out, N, V, tile, G);
}